// round 13
// baseline (speedup 1.0000x reference)
#include <cuda_runtime.h>
#include <cuda_fp16.h>
#include <cstdint>

// ====================== tile/pipeline constants ======================
// CTA: 128 threads (4 warps 2x2), tile 128 couts x 112 pixels (2 output rows)
// Superstage = 64 ci: A 16384 B (128 rows x 128B) + B 14336 B (112 rows x 128B)
#define STG      30720
#define STAGES   2
#define SMEM_DYN (STAGES * STG + 128)

// ====================== device scratch ======================
__device__ __align__(16) __half g_x[(size_t)32 * 58 * 58 * 256];  // padded NHWC fp16
__device__ __align__(16) __half g_w[(size_t)9 * 256 * 256];       // [tap][co][ci] = +-1

// ====================== helpers ======================
__device__ __forceinline__ uint32_t smem_u32(const void* p) {
    uint32_t a;
    asm("{ .reg .u64 t; cvta.to.shared.u64 t, %1; cvt.u32.u64 %0, t; }" : "=r"(a) : "l"(p));
    return a;
}
__device__ __forceinline__ void cp16(uint32_t d, const void* s) {
    asm volatile("cp.async.cg.shared.global [%0], [%1], 16;" :: "r"(d), "l"(s) : "memory");
}
__device__ __forceinline__ void ldsm_x4(uint32_t* r, uint32_t a) {
    asm volatile("ldmatrix.sync.aligned.m8n8.x4.shared.b16 {%0,%1,%2,%3}, [%4];"
                 : "=r"(r[0]), "=r"(r[1]), "=r"(r[2]), "=r"(r[3]) : "r"(a));
}
__device__ __forceinline__ void ldsm_x2(uint32_t* r, uint32_t a) {
    asm volatile("ldmatrix.sync.aligned.m8n8.x2.shared.b16 {%0,%1}, [%2];"
                 : "=r"(r[0]), "=r"(r[1]) : "r"(a));
}
__device__ __forceinline__ void mma16816(float* c, uint32_t a0, uint32_t a1, uint32_t a2,
                                         uint32_t a3, uint32_t b0, uint32_t b1) {
    asm volatile(
        "mma.sync.aligned.m16n8k16.row.col.f32.f16.f16.f32 "
        "{%0,%1,%2,%3}, {%4,%5,%6,%7}, {%8,%9}, {%0,%1,%2,%3};"
        : "+f"(c[0]), "+f"(c[1]), "+f"(c[2]), "+f"(c[3])
        : "r"(a0), "r"(a1), "r"(a2), "r"(a3), "r"(b0), "r"(b1));
}

// ====================== prep kernels ======================
__global__ void zero_border_kernel() {
    const int n = blockIdx.x;                       // 32 images
    __half* xb = g_x + (size_t)n * 861184;
    for (int c = threadIdx.x; c < 7296; c += 256) { // 228 border px * 32 uint4
        int px = c >> 5, q = c & 31;
        int h, w;
        if (px < 58)       { h = 0;        w = px; }
        else if (px < 116) { h = 57;       w = px - 58; }
        else if (px < 172) { h = px - 115; w = 0; }
        else               { h = px - 171; w = 57; }
        reinterpret_cast<uint4*>(xb + ((size_t)h * 58 + w) * 256)[q] =
            make_uint4(0u, 0u, 0u, 0u);
    }
}

// x NCHW f32 -> g_x padded NHWC fp16 (linear ci), vectorized. grid 32*56*2, 256 thr.
__global__ void prep_x_kernel(const float* __restrict__ x) {
    __shared__ float tile[128][57];
    const int b  = blockIdx.x;
    const int ch = b & 1;
    const int h  = (b >> 1) % 56;
    const int n  = (b >> 1) / 56;
    // reads: 128 ci-rows x 14 float4 (56 floats/row), coalesced in 224B runs
    const float4* src4 = reinterpret_cast<const float4*>(
        x + (size_t)(n * 256 + ch * 128) * 3136 + h * 56);
    for (int i = threadIdx.x; i < 128 * 14; i += 256) {
        int ci = i / 14, f = i - 14 * ci;
        float4 v = src4[(size_t)ci * 784 + f];
        tile[ci][4 * f + 0] = v.x;
        tile[ci][4 * f + 1] = v.y;
        tile[ci][4 * f + 2] = v.z;
        tile[ci][4 * f + 3] = v.w;
    }
    __syncthreads();
    // writes: per (w, cq): 8 consecutive ci as one uint4 (16B), coalesced 256B runs
    __half* dst = g_x + (size_t)n * 861184 + ((h + 1) * 58 + 1) * 256 + ch * 128;
    for (int j = threadIdx.x; j < 56 * 16; j += 256) {
        int w = j >> 4, cq = j & 15;
        int c0 = cq * 8;
        uint4 o;
        o.x = __half2_raw(__floats2half2_rn(tile[c0 + 0][w], tile[c0 + 1][w])).x |
              ((uint32_t)__half2_raw(__floats2half2_rn(tile[c0 + 0][w], tile[c0 + 1][w])).y << 16);
        // pack via half2 reinterpret (cleaner):
        __half2 p0 = __floats2half2_rn(tile[c0 + 0][w], tile[c0 + 1][w]);
        __half2 p1 = __floats2half2_rn(tile[c0 + 2][w], tile[c0 + 3][w]);
        __half2 p2 = __floats2half2_rn(tile[c0 + 4][w], tile[c0 + 5][w]);
        __half2 p3 = __floats2half2_rn(tile[c0 + 6][w], tile[c0 + 7][w]);
        o.x = *reinterpret_cast<uint32_t*>(&p0);
        o.y = *reinterpret_cast<uint32_t*>(&p1);
        o.z = *reinterpret_cast<uint32_t*>(&p2);
        o.w = *reinterpret_cast<uint32_t*>(&p3);
        *reinterpret_cast<uint4*>(dst + (size_t)w * 256 + c0) = o;
    }
}

// weight [co][ci][3][3] f32 -> g_w[tap][co][ci] = +-1 fp16. grid 2304, 256 thr.
__global__ void prep_w_kernel(const float* __restrict__ w) {
    int idx = blockIdx.x * 256 + threadIdx.x;             // co*2304 + ci*9 + tap
    int co  = idx / 2304;
    int r   = idx - co * 2304;
    int ci  = r / 9;
    int tap = r - ci * 9;
    g_w[(size_t)(tap * 256 + co) * 256 + ci] = __float2half(w[idx] >= 0.f ? 1.f : -1.f);
}

// ====================== main kernel ======================
// grid 1792 = 2 cout-halves * 28 row-pairs * 32 images; 128 threads (4 warps 2x2).
// Warp tile 64x56: 4 m16-frags x 7 n8-frags, 4 ksteps per 64-ci superstage.
// Smem: 128B rows, 16B bank index = chunk ^ (row&7) (ldmatrix conflict-free);
// kstep k selects chunks {2k,2k+1} via address XOR (k<<5).
// Schedule: post-barrier LDSM first; prefetch cp.asyncs slide into k0's MMA shadow.
__global__ void __launch_bounds__(128, 3)
bconv_main_kernel(const float* __restrict__ bias, float* __restrict__ out) {
    extern __shared__ char dsm[];
    const uint32_t base = (smem_u32(dsm) + 127u) & ~127u;

    const int tid  = threadIdx.x;
    const int lane = tid & 31;
    const int wid  = tid >> 5;
    const int g    = lane >> 2;
    const int t    = lane & 3;
    const int wm   = wid >> 1;     // 0..1  (m warp half)
    const int wn   = wid & 1;      // 0..1  (output row within pair)

    const int bid = blockIdx.x;
    const int mb  = bid & 1;
    const int rp  = (bid >> 1) % 28;
    const int n   = bid / 56;
    const int h0  = rp * 2;

    const __half* xn = g_x + (size_t)n * 861184;

    // ---- cp.async affine bases (16B chunks; row&7 invariant across i since step=16) ----
    const int r0  = tid >> 3;                 // base row 0..15
    const int cbk = tid & 7;                  // chunk within 128B row
    const uint32_t cb8 = (uint32_t)(cbk * 8); // element offset of chunk
    const uint32_t swz = (uint32_t)((cbk ^ (r0 & 7)) << 4);
    const uint32_t aD0 = (uint32_t)(r0 * 128) + swz;
    const uint32_t bD0 = 16384u + aD0;
    const uint32_t aG0 = (uint32_t)((mb * 128 + r0) * 256) + cb8;

    auto load_A = [&](int ss, uint32_t sb) {
        int tap = ss >> 2, kc2 = ss & 3;
        const __half* wp = g_w + tap * 65536 + kc2 * 64 + aG0;
#pragma unroll
        for (int i = 0; i < 8; i++)
            cp16(sb + aD0 + (uint32_t)(i * 2048), wp + i * 4096);
    };
    auto load_B = [&](int ss, uint32_t sb) {
        int tap = ss >> 2, kc2 = ss & 3;
        int dh  = tap / 3, dw = tap - 3 * dh;
        uint32_t bgc = (uint32_t)((((h0 + dh) * 58 + dw) * 256) + kc2 * 64) + cb8;
#pragma unroll
        for (int i = 0; i < 7; i++) {
            int prow = r0 + 16 * i;
            uint32_t off = bgc + (uint32_t)(prow * 256) + (prow >= 56 ? 512u : 0u);
            cp16(sb + bD0 + (uint32_t)(i * 2048), xn + off);
        }
        asm volatile("cp.async.commit_group;" ::: "memory");
    };

    // ---- ldmatrix lane addresses (kstep 0; kstep k = XOR k<<5) ----
    uint32_t rA[4];
    {
        int rl   = (lane & 7) + ((lane >> 3) & 1) * 8;
        int half = lane >> 4;
#pragma unroll
        for (int mi = 0; mi < 4; mi++) {
            int row = wm * 64 + mi * 16 + rl;
            rA[mi] = (uint32_t)(row * 128 + ((half ^ (row & 7)) << 4));
        }
    }
    uint32_t rB[4];
    {
        int pl   = (lane & 7) + (lane >> 4) * 8;
        int half = (lane >> 3) & 1;
#pragma unroll
        for (int pi = 0; pi < 3; pi++) {
            int pix = wn * 56 + pi * 16 + pl;
            rB[pi] = 16384u + (uint32_t)(pix * 128 + ((half ^ (pix & 7)) << 4));
        }
        int pix6 = wn * 56 + 48 + (lane & 7);
        rB[3] = 16384u + (uint32_t)(pix6 * 128 + ((half ^ (pix6 & 7)) << 4));
    }

    float acc[4][7][4];
#pragma unroll
    for (int mi = 0; mi < 4; mi++)
#pragma unroll
        for (int ni = 0; ni < 7; ni++)
#pragma unroll
            for (int k = 0; k < 4; k++) acc[mi][ni][k] = 0.f;

    // ---- prologue: superstage 0 ----
    load_A(0, base);
    load_B(0, base);
    asm volatile("cp.async.wait_group 0;" ::: "memory");
    __syncthreads();

    // ---- mainloop: 36 superstages, 2 buffers ----
    for (int ss = 0; ss < 36; ss++) {
        const uint32_t sb = base + (uint32_t)((ss & 1) * STG);
        const uint32_t pb = base + (uint32_t)(((ss + 1) & 1) * STG);
        const bool pf = (ss < 35);

#pragma unroll
        for (int k = 0; k < 4; k++) {
            const uint32_t xr = (uint32_t)(k << 5);
            uint32_t a[4][4];
#pragma unroll
            for (int mi = 0; mi < 4; mi++) ldsm_x4(a[mi], sb + (rA[mi] ^ xr));
            if (k == 0 && pf) load_A(ss + 1, pb);   // A prefetch in k0 LDSM/MMA shadow
#pragma unroll
            for (int pi = 0; pi < 3; pi++) {
                uint32_t b[4];
                ldsm_x4(b, sb + (rB[pi] ^ xr));
#pragma unroll
                for (int mi = 0; mi < 4; mi++) {
                    mma16816(acc[mi][2 * pi],     a[mi][0], a[mi][1], a[mi][2], a[mi][3], b[0], b[1]);
                    mma16816(acc[mi][2 * pi + 1], a[mi][0], a[mi][1], a[mi][2], a[mi][3], b[2], b[3]);
                }
            }
            uint32_t b6[2];
            ldsm_x2(b6, sb + (rB[3] ^ xr));
#pragma unroll
            for (int mi = 0; mi < 4; mi++)
                mma16816(acc[mi][6], a[mi][0], a[mi][1], a[mi][2], a[mi][3], b6[0], b6[1]);
            if (k == 0 && pf) load_B(ss + 1, pb);   // B prefetch + commit after k0 MMAs
        }
        asm volatile("cp.async.wait_group 0;" ::: "memory");
        __syncthreads();
    }

    // ---- epilogue: registers -> gmem (float2), + binarized bias ----
    const int h = h0 + wn;
#pragma unroll
    for (int mi = 0; mi < 4; mi++) {
        int mlo = mb * 128 + wm * 64 + mi * 16 + g;
        float blo = (bias[mlo]     >= 0.f) ? 1.f : -1.f;
        float bhi = (bias[mlo + 8] >= 0.f) ? 1.f : -1.f;
        size_t olo = ((size_t)(n * 256 + mlo)) * 3136 + h * 56;
        size_t ohi = olo + (size_t)8 * 3136;
#pragma unroll
        for (int ni = 0; ni < 7; ni++) {
            int w = ni * 8 + 2 * t;
            float2 v0 = make_float2(acc[mi][ni][0] + blo, acc[mi][ni][1] + blo);
            float2 v1 = make_float2(acc[mi][ni][2] + bhi, acc[mi][ni][3] + bhi);
            *reinterpret_cast<float2*>(out + olo + w) = v0;
            *reinterpret_cast<float2*>(out + ohi + w) = v1;
        }
    }
}

// ====================== launch ======================
extern "C" void kernel_launch(void* const* d_in, const int* in_sizes, int n_in,
                              void* d_out, int out_size) {
    const float* x    = (const float*)d_in[0];
    const float* w    = (const float*)d_in[1];
    const float* bias = (const float*)d_in[2];
    float* out        = (float*)d_out;

    cudaFuncSetAttribute(bconv_main_kernel,
                         cudaFuncAttributeMaxDynamicSharedMemorySize, SMEM_DYN);

    zero_border_kernel<<<32, 256>>>();
    prep_x_kernel<<<32 * 56 * 2, 256>>>(x);
    prep_w_kernel<<<2304, 256>>>(w);
    bconv_main_kernel<<<1792, 128, SMEM_DYN>>>(bias, out);
}

// round 14
// speedup vs baseline: 1.0280x; 1.0280x over previous
#include <cuda_runtime.h>
#include <cuda_fp16.h>
#include <cstdint>

// ====================== tile/pipeline constants ======================
// CTA: 128 threads (4 warps 2x2), tile 128 couts x 112 pixels (2 output rows)
// Superstage = 64 ci: A 16384 B (128 rows x 128B) + B 14336 B (112 rows x 128B)
#define STG      30720
#define STAGES   2
#define SMEM_DYN (STAGES * STG + 128)

// ====================== device scratch ======================
__device__ __align__(16) __half g_x[(size_t)32 * 58 * 58 * 256];  // padded NHWC fp16
__device__ __align__(16) __half g_w[(size_t)9 * 256 * 256];       // [tap][co][ci] = +-1

// ====================== helpers ======================
__device__ __forceinline__ uint32_t smem_u32(const void* p) {
    uint32_t a;
    asm("{ .reg .u64 t; cvta.to.shared.u64 t, %1; cvt.u32.u64 %0, t; }" : "=r"(a) : "l"(p));
    return a;
}
__device__ __forceinline__ void cp16(uint32_t d, const void* s) {
    asm volatile("cp.async.cg.shared.global [%0], [%1], 16;" :: "r"(d), "l"(s) : "memory");
}
__device__ __forceinline__ void ldsm_x4(uint32_t* r, uint32_t a) {
    asm volatile("ldmatrix.sync.aligned.m8n8.x4.shared.b16 {%0,%1,%2,%3}, [%4];"
                 : "=r"(r[0]), "=r"(r[1]), "=r"(r[2]), "=r"(r[3]) : "r"(a));
}
__device__ __forceinline__ void ldsm_x2(uint32_t* r, uint32_t a) {
    asm volatile("ldmatrix.sync.aligned.m8n8.x2.shared.b16 {%0,%1}, [%2];"
                 : "=r"(r[0]), "=r"(r[1]) : "r"(a));
}
__device__ __forceinline__ void mma16816(float* c, uint32_t a0, uint32_t a1, uint32_t a2,
                                         uint32_t a3, uint32_t b0, uint32_t b1) {
    asm volatile(
        "mma.sync.aligned.m16n8k16.row.col.f32.f16.f16.f32 "
        "{%0,%1,%2,%3}, {%4,%5,%6,%7}, {%8,%9}, {%0,%1,%2,%3};"
        : "+f"(c[0]), "+f"(c[1]), "+f"(c[2]), "+f"(c[3])
        : "r"(a0), "r"(a1), "r"(a2), "r"(a3), "r"(b0), "r"(b1));
}

// ====================== prep kernels ======================
__global__ void zero_border_kernel() {
    const int n = blockIdx.x;                       // 32 images
    __half* xb = g_x + (size_t)n * 861184;
    for (int c = threadIdx.x; c < 7296; c += 256) { // 228 border px * 32 uint4
        int px = c >> 5, q = c & 31;
        int h, w;
        if (px < 58)       { h = 0;        w = px; }
        else if (px < 116) { h = 57;       w = px - 58; }
        else if (px < 172) { h = px - 115; w = 0; }
        else               { h = px - 171; w = 57; }
        reinterpret_cast<uint4*>(xb + ((size_t)h * 58 + w) * 256)[q] =
            make_uint4(0u, 0u, 0u, 0u);
    }
}

// x NCHW f32 -> g_x padded NHWC fp16 (linear ci). grid 32*56*2, 256 thr.
__global__ void prep_x_kernel(const float* __restrict__ x) {
    __shared__ float tile[128][57];
    const int b  = blockIdx.x;
    const int ch = b & 1;
    const int h  = (b >> 1) % 56;
    const int n  = (b >> 1) / 56;
    const float* src = x + (size_t)(n * 256 + ch * 128) * 3136 + h * 56;
    for (int i = threadIdx.x; i < 128 * 56; i += 256) {
        int ci = i / 56, w = i - 56 * ci;
        tile[ci][w] = src[(size_t)ci * 3136 + w];
    }
    __syncthreads();
    __half* dst = g_x + (size_t)n * 861184 + ((h + 1) * 58 + 1) * 256;
    for (int j = threadIdx.x; j < 64 * 56; j += 256) {
        int w  = j >> 6, cp = j & 63;
        int ci = ch * 128 + 2 * cp;
        __half2 v = __floats2half2_rn(tile[2 * cp][w], tile[2 * cp + 1][w]);
        *reinterpret_cast<__half2*>(dst + (size_t)w * 256 + ci) = v;
    }
}

// weight [co][ci][3][3] f32 -> g_w[tap][co][ci] = +-1 fp16. grid 2304, 256 thr.
__global__ void prep_w_kernel(const float* __restrict__ w) {
    int idx = blockIdx.x * 256 + threadIdx.x;             // co*2304 + ci*9 + tap
    int co  = idx / 2304;
    int r   = idx - co * 2304;
    int ci  = r / 9;
    int tap = r - ci * 9;
    g_w[(size_t)(tap * 256 + co) * 256 + ci] = __float2half(w[idx] >= 0.f ? 1.f : -1.f);
}

// ====================== main kernel ======================
// grid 1792 = 2 cout-halves * 28 row-pairs * 32 images; 128 threads (4 warps 2x2).
// Warp tile 64x56: 4 m16-frags x 7 n8-frags, 4 ksteps per 64-ci superstage.
// Smem: 128B rows, 16B bank index = chunk ^ (row&7) (ldmatrix conflict-free);
// kstep k selects chunks {2k,2k+1} via address XOR (k<<5).
// Split barriers: bar.arrive after last read of each smem region (k3), bar.sync
// just before that region is overwritten at the next iteration's top — barrier
// convergence hides under MMA issue; no fragment lives across a blocking point.
__global__ void __launch_bounds__(128, 3)
bconv_main_kernel(const float* __restrict__ bias, float* __restrict__ out) {
    extern __shared__ char dsm[];
    const uint32_t base = (smem_u32(dsm) + 127u) & ~127u;

    const int tid  = threadIdx.x;
    const int lane = tid & 31;
    const int wid  = tid >> 5;
    const int g    = lane >> 2;
    const int t    = lane & 3;
    const int wm   = wid >> 1;     // 0..1  (m warp half)
    const int wn   = wid & 1;      // 0..1  (output row within pair)

    const int bid = blockIdx.x;
    const int mb  = bid & 1;
    const int rp  = (bid >> 1) % 28;
    const int n   = bid / 56;
    const int h0  = rp * 2;

    const __half* xn = g_x + (size_t)n * 861184;

    // ---- cp.async affine bases (16B chunks; row&7 invariant across i since step=16) ----
    const int r0  = tid >> 3;                 // base row 0..15
    const int cbk = tid & 7;                  // chunk within 128B row
    const uint32_t cb8 = (uint32_t)(cbk * 8); // element offset of chunk
    const uint32_t swz = (uint32_t)((cbk ^ (r0 & 7)) << 4);
    const uint32_t aD0 = (uint32_t)(r0 * 128) + swz;
    const uint32_t bD0 = 16384u + aD0;
    const uint32_t aG0 = (uint32_t)((mb * 128 + r0) * 256) + cb8;

    auto load_A = [&](int ss, uint32_t sb) {
        int tap = ss >> 2, kc2 = ss & 3;
        const __half* wp = g_w + tap * 65536 + kc2 * 64 + aG0;
#pragma unroll
        for (int i = 0; i < 8; i++)
            cp16(sb + aD0 + (uint32_t)(i * 2048), wp + i * 4096);
    };
    auto load_B = [&](int ss, uint32_t sb) {
        int tap = ss >> 2, kc2 = ss & 3;
        int dh  = tap / 3, dw = tap - 3 * dh;
        uint32_t bgc = (uint32_t)((((h0 + dh) * 58 + dw) * 256) + kc2 * 64) + cb8;
#pragma unroll
        for (int i = 0; i < 7; i++) {
            int prow = r0 + 16 * i;
            uint32_t off = bgc + (uint32_t)(prow * 256) + (prow >= 56 ? 512u : 0u);
            cp16(sb + bD0 + (uint32_t)(i * 2048), xn + off);
        }
        asm volatile("cp.async.commit_group;" ::: "memory");
    };

    // ---- ldmatrix lane addresses (kstep 0; kstep k = XOR k<<5) ----
    uint32_t rA[4];
    {
        int rl   = (lane & 7) + ((lane >> 3) & 1) * 8;
        int half = lane >> 4;
#pragma unroll
        for (int mi = 0; mi < 4; mi++) {
            int row = wm * 64 + mi * 16 + rl;
            rA[mi] = (uint32_t)(row * 128 + ((half ^ (row & 7)) << 4));
        }
    }
    uint32_t rB[4];
    {
        int pl   = (lane & 7) + (lane >> 4) * 8;
        int half = (lane >> 3) & 1;
#pragma unroll
        for (int pi = 0; pi < 3; pi++) {
            int pix = wn * 56 + pi * 16 + pl;
            rB[pi] = 16384u + (uint32_t)(pix * 128 + ((half ^ (pix & 7)) << 4));
        }
        int pix6 = wn * 56 + 48 + (lane & 7);
        rB[3] = 16384u + (uint32_t)(pix6 * 128 + ((half ^ (pix6 & 7)) << 4));
    }

    float acc[4][7][4];
#pragma unroll
    for (int mi = 0; mi < 4; mi++)
#pragma unroll
        for (int ni = 0; ni < 7; ni++)
#pragma unroll
            for (int k = 0; k < 4; k++) acc[mi][ni][k] = 0.f;

    // ---- prologue: superstage 0, pre-arm both barriers ----
    load_A(0, base);
    load_B(0, base);
    asm volatile("cp.async.wait_group 0;" ::: "memory");
    __syncthreads();
    asm volatile("bar.arrive 1, 256;" ::: "memory");
    asm volatile("bar.arrive 2, 256;" ::: "memory");

    // ---- mainloop: 36 superstages, 2 buffers ----
    for (int ss = 0; ss < 36; ss++) {
        const uint32_t sb = base + (uint32_t)((ss & 1) * STG);
        const uint32_t pb = base + (uint32_t)(((ss + 1) & 1) * STG);

        asm volatile("bar.sync 1, 256;" ::: "memory");   // A-region of pb free
        if (ss < 35) load_A(ss + 1, pb);
        asm volatile("bar.sync 2, 256;" ::: "memory");   // B-region of pb free
        if (ss < 35) load_B(ss + 1, pb);                 // includes commit
        else asm volatile("cp.async.commit_group;" ::: "memory");

        // ---- ksteps 0..2 ----
#pragma unroll
        for (int k = 0; k < 3; k++) {
            const uint32_t xr = (uint32_t)(k << 5);
            uint32_t a[4][4];
#pragma unroll
            for (int mi = 0; mi < 4; mi++) ldsm_x4(a[mi], sb + (rA[mi] ^ xr));
#pragma unroll
            for (int pi = 0; pi < 3; pi++) {
                uint32_t b[4];
                ldsm_x4(b, sb + (rB[pi] ^ xr));
#pragma unroll
                for (int mi = 0; mi < 4; mi++) {
                    mma16816(acc[mi][2 * pi],     a[mi][0], a[mi][1], a[mi][2], a[mi][3], b[0], b[1]);
                    mma16816(acc[mi][2 * pi + 1], a[mi][0], a[mi][1], a[mi][2], a[mi][3], b[2], b[3]);
                }
            }
            uint32_t b6[2];
            ldsm_x2(b6, sb + (rB[3] ^ xr));
#pragma unroll
            for (int mi = 0; mi < 4; mi++)
                mma16816(acc[mi][6], a[mi][0], a[mi][1], a[mi][2], a[mi][3], b6[0], b6[1]);
        }

        // ---- kstep 3: arrive-after-last-read placement ----
        {
            const uint32_t xr = 0x60u;
            uint32_t a[4][4];
#pragma unroll
            for (int mi = 0; mi < 4; mi++) ldsm_x4(a[mi], sb + (rA[mi] ^ xr));
            asm volatile("bar.arrive 1, 256;" ::: "memory");   // A-region reads done

            uint32_t b6[2];
            ldsm_x2(b6, sb + (rB[3] ^ xr));
#pragma unroll
            for (int mi = 0; mi < 4; mi++)
                mma16816(acc[mi][6], a[mi][0], a[mi][1], a[mi][2], a[mi][3], b6[0], b6[1]);
#pragma unroll
            for (int pi = 0; pi < 2; pi++) {
                uint32_t b[4];
                ldsm_x4(b, sb + (rB[pi] ^ xr));
#pragma unroll
                for (int mi = 0; mi < 4; mi++) {
                    mma16816(acc[mi][2 * pi],     a[mi][0], a[mi][1], a[mi][2], a[mi][3], b[0], b[1]);
                    mma16816(acc[mi][2 * pi + 1], a[mi][0], a[mi][1], a[mi][2], a[mi][3], b[2], b[3]);
                }
            }
            uint32_t b2[4];
            ldsm_x4(b2, sb + (rB[2] ^ xr));                    // last B-region read
            asm volatile("cp.async.wait_group 0;" ::: "memory"); // own G_{ss+1} landed
            asm volatile("bar.arrive 2, 256;" ::: "memory");   // B-region reads done
#pragma unroll
            for (int mi = 0; mi < 4; mi++) {
                mma16816(acc[mi][4], a[mi][0], a[mi][1], a[mi][2], a[mi][3], b2[0], b2[1]);
                mma16816(acc[mi][5], a[mi][0], a[mi][1], a[mi][2], a[mi][3], b2[2], b2[3]);
            }
        }
    }

    // ---- epilogue: registers -> gmem (float2), + binarized bias ----
    const int h = h0 + wn;
#pragma unroll
    for (int mi = 0; mi < 4; mi++) {
        int mlo = mb * 128 + wm * 64 + mi * 16 + g;
        float blo = (bias[mlo]     >= 0.f) ? 1.f : -1.f;
        float bhi = (bias[mlo + 8] >= 0.f) ? 1.f : -1.f;
        size_t olo = ((size_t)(n * 256 + mlo)) * 3136 + h * 56;
        size_t ohi = olo + (size_t)8 * 3136;
#pragma unroll
        for (int ni = 0; ni < 7; ni++) {
            int w = ni * 8 + 2 * t;
            float2 v0 = make_float2(acc[mi][ni][0] + blo, acc[mi][ni][1] + blo);
            float2 v1 = make_float2(acc[mi][ni][2] + bhi, acc[mi][ni][3] + bhi);
            *reinterpret_cast<float2*>(out + olo + w) = v0;
            *reinterpret_cast<float2*>(out + ohi + w) = v1;
        }
    }
}

// ====================== launch ======================
extern "C" void kernel_launch(void* const* d_in, const int* in_sizes, int n_in,
                              void* d_out, int out_size) {
    const float* x    = (const float*)d_in[0];
    const float* w    = (const float*)d_in[1];
    const float* bias = (const float*)d_in[2];
    float* out        = (float*)d_out;

    cudaFuncSetAttribute(bconv_main_kernel,
                         cudaFuncAttributeMaxDynamicSharedMemorySize, SMEM_DYN);

    zero_border_kernel<<<32, 256>>>();
    prep_x_kernel<<<32 * 56 * 2, 256>>>(x);
    prep_w_kernel<<<2304, 256>>>(w);
    bconv_main_kernel<<<1792, 128, SMEM_DYN>>>(bias, out);
}

// round 15
// speedup vs baseline: 1.0292x; 1.0012x over previous
#include <cuda_runtime.h>
#include <cuda_fp16.h>
#include <cstdint>

// ====================== tile/pipeline constants ======================
// CTA: 128 threads (4 warps 2x2), tile 128 couts x 112 pixels (2 output rows)
// Superstage = 64 ci: A 16384 B (128 rows x 128B) + B 14336 B (112 rows x 128B)
#define STG      30720
#define STAGES   2
#define SMEM_DYN (STAGES * STG + 128)

// ====================== device scratch ======================
__device__ __align__(16) __half g_x[(size_t)32 * 58 * 58 * 256];  // padded NHWC fp16
__device__ __align__(16) __half g_w[(size_t)9 * 256 * 256];       // [tap][co][ci] = +-1

// ====================== helpers ======================
__device__ __forceinline__ uint32_t smem_u32(const void* p) {
    uint32_t a;
    asm("{ .reg .u64 t; cvta.to.shared.u64 t, %1; cvt.u32.u64 %0, t; }" : "=r"(a) : "l"(p));
    return a;
}
__device__ __forceinline__ void cp16(uint32_t d, const void* s) {
    asm volatile("cp.async.cg.shared.global [%0], [%1], 16;" :: "r"(d), "l"(s) : "memory");
}
__device__ __forceinline__ void ldsm_x4(uint32_t* r, uint32_t a) {
    asm volatile("ldmatrix.sync.aligned.m8n8.x4.shared.b16 {%0,%1,%2,%3}, [%4];"
                 : "=r"(r[0]), "=r"(r[1]), "=r"(r[2]), "=r"(r[3]) : "r"(a));
}
__device__ __forceinline__ void ldsm_x2(uint32_t* r, uint32_t a) {
    asm volatile("ldmatrix.sync.aligned.m8n8.x2.shared.b16 {%0,%1}, [%2];"
                 : "=r"(r[0]), "=r"(r[1]) : "r"(a));
}
__device__ __forceinline__ void mma16816(float* c, uint32_t a0, uint32_t a1, uint32_t a2,
                                         uint32_t a3, uint32_t b0, uint32_t b1) {
    asm volatile(
        "mma.sync.aligned.m16n8k16.row.col.f32.f16.f16.f32 "
        "{%0,%1,%2,%3}, {%4,%5,%6,%7}, {%8,%9}, {%0,%1,%2,%3};"
        : "+f"(c[0]), "+f"(c[1]), "+f"(c[2]), "+f"(c[3])
        : "r"(a0), "r"(a1), "r"(a2), "r"(a3), "r"(b0), "r"(b1));
}

// ====================== prep kernels ======================
__global__ void zero_border_kernel() {
    const int n = blockIdx.x;                       // 32 images
    __half* xb = g_x + (size_t)n * 861184;
    for (int c = threadIdx.x; c < 7296; c += 256) { // 228 border px * 32 uint4
        int px = c >> 5, q = c & 31;
        int h, w;
        if (px < 58)       { h = 0;        w = px; }
        else if (px < 116) { h = 57;       w = px - 58; }
        else if (px < 172) { h = px - 115; w = 0; }
        else               { h = px - 171; w = 57; }
        reinterpret_cast<uint4*>(xb + ((size_t)h * 58 + w) * 256)[q] =
            make_uint4(0u, 0u, 0u, 0u);
    }
}

// x NCHW f32 -> g_x padded NHWC fp16 (linear ci). grid 32*56*2, 256 thr.
__global__ void prep_x_kernel(const float* __restrict__ x) {
    __shared__ float tile[128][57];
    const int b  = blockIdx.x;
    const int ch = b & 1;
    const int h  = (b >> 1) % 56;
    const int n  = (b >> 1) / 56;
    const float* src = x + (size_t)(n * 256 + ch * 128) * 3136 + h * 56;
    for (int i = threadIdx.x; i < 128 * 56; i += 256) {
        int ci = i / 56, w = i - 56 * ci;
        tile[ci][w] = src[(size_t)ci * 3136 + w];
    }
    __syncthreads();
    __half* dst = g_x + (size_t)n * 861184 + ((h + 1) * 58 + 1) * 256;
    for (int j = threadIdx.x; j < 64 * 56; j += 256) {
        int w  = j >> 6, cp = j & 63;
        int ci = ch * 128 + 2 * cp;
        __half2 v = __floats2half2_rn(tile[2 * cp][w], tile[2 * cp + 1][w]);
        *reinterpret_cast<__half2*>(dst + (size_t)w * 256 + ci) = v;
    }
}

// weight [co][ci][3][3] f32 -> g_w[tap][co][ci] = +-1 fp16. grid 2304, 256 thr.
__global__ void prep_w_kernel(const float* __restrict__ w) {
    int idx = blockIdx.x * 256 + threadIdx.x;             // co*2304 + ci*9 + tap
    int co  = idx / 2304;
    int r   = idx - co * 2304;
    int ci  = r / 9;
    int tap = r - ci * 9;
    g_w[(size_t)(tap * 256 + co) * 256 + ci] = __float2half(w[idx] >= 0.f ? 1.f : -1.f);
}

// ====================== main kernel ======================
// grid 1792 = 2 cout-halves * 28 row-pairs * 32 images; 128 threads (4 warps 2x2).
// Warp tile 64x56: 4 m16-frags x 7 n8-frags, 4 ksteps per 64-ci superstage.
// Smem: 128B rows, 16B bank index = chunk ^ (row&7) (ldmatrix conflict-free);
// kstep k selects chunks {2k,2k+1} via address XOR (k<<5).
// Split barriers: bar.arrive after last read of each smem region (k3), bar.sync
// just before that region is overwritten at the next iteration's top — barrier
// convergence hides under MMA issue; no fragment lives across a blocking point.
__global__ void __launch_bounds__(128, 3)
bconv_main_kernel(const float* __restrict__ bias, float* __restrict__ out) {
    extern __shared__ char dsm[];
    const uint32_t base = (smem_u32(dsm) + 127u) & ~127u;

    const int tid  = threadIdx.x;
    const int lane = tid & 31;
    const int wid  = tid >> 5;
    const int g    = lane >> 2;
    const int t    = lane & 3;
    const int wm   = wid >> 1;     // 0..1  (m warp half)
    const int wn   = wid & 1;      // 0..1  (output row within pair)

    const int bid = blockIdx.x;
    const int mb  = bid & 1;
    const int rp  = (bid >> 1) % 28;
    const int n   = bid / 56;
    const int h0  = rp * 2;

    const __half* xn = g_x + (size_t)n * 861184;

    // ---- cp.async affine bases (16B chunks; row&7 invariant across i since step=16) ----
    const int r0  = tid >> 3;                 // base row 0..15
    const int cbk = tid & 7;                  // chunk within 128B row
    const uint32_t cb8 = (uint32_t)(cbk * 8); // element offset of chunk
    const uint32_t swz = (uint32_t)((cbk ^ (r0 & 7)) << 4);
    const uint32_t aD0 = (uint32_t)(r0 * 128) + swz;
    const uint32_t bD0 = 16384u + aD0;
    const uint32_t aG0 = (uint32_t)((mb * 128 + r0) * 256) + cb8;

    auto load_A = [&](int ss, uint32_t sb) {
        int tap = ss >> 2, kc2 = ss & 3;
        const __half* wp = g_w + tap * 65536 + kc2 * 64 + aG0;
#pragma unroll
        for (int i = 0; i < 8; i++)
            cp16(sb + aD0 + (uint32_t)(i * 2048), wp + i * 4096);
    };
    auto load_B = [&](int ss, uint32_t sb) {
        int tap = ss >> 2, kc2 = ss & 3;
        int dh  = tap / 3, dw = tap - 3 * dh;
        uint32_t bgc = (uint32_t)((((h0 + dh) * 58 + dw) * 256) + kc2 * 64) + cb8;
#pragma unroll
        for (int i = 0; i < 7; i++) {
            int prow = r0 + 16 * i;
            uint32_t off = bgc + (uint32_t)(prow * 256) + (prow >= 56 ? 512u : 0u);
            cp16(sb + bD0 + (uint32_t)(i * 2048), xn + off);
        }
        asm volatile("cp.async.commit_group;" ::: "memory");
    };

    // ---- ldmatrix lane addresses (kstep 0; kstep k = XOR k<<5) ----
    uint32_t rA[4];
    {
        int rl   = (lane & 7) + ((lane >> 3) & 1) * 8;
        int half = lane >> 4;
#pragma unroll
        for (int mi = 0; mi < 4; mi++) {
            int row = wm * 64 + mi * 16 + rl;
            rA[mi] = (uint32_t)(row * 128 + ((half ^ (row & 7)) << 4));
        }
    }
    uint32_t rB[4];
    {
        int pl   = (lane & 7) + (lane >> 4) * 8;
        int half = (lane >> 3) & 1;
#pragma unroll
        for (int pi = 0; pi < 3; pi++) {
            int pix = wn * 56 + pi * 16 + pl;
            rB[pi] = 16384u + (uint32_t)(pix * 128 + ((half ^ (pix & 7)) << 4));
        }
        int pix6 = wn * 56 + 48 + (lane & 7);
        rB[3] = 16384u + (uint32_t)(pix6 * 128 + ((half ^ (pix6 & 7)) << 4));
    }

    float acc[4][7][4];
#pragma unroll
    for (int mi = 0; mi < 4; mi++)
#pragma unroll
        for (int ni = 0; ni < 7; ni++)
#pragma unroll
            for (int k = 0; k < 4; k++) acc[mi][ni][k] = 0.f;

    // ---- prologue: superstage 0, pre-arm both barriers ----
    load_A(0, base);
    load_B(0, base);
    asm volatile("cp.async.wait_group 0;" ::: "memory");
    __syncthreads();
    asm volatile("bar.arrive 1, 256;" ::: "memory");
    asm volatile("bar.arrive 2, 256;" ::: "memory");

    // ---- mainloop: 36 superstages, 2 buffers ----
    for (int ss = 0; ss < 36; ss++) {
        const uint32_t sb = base + (uint32_t)((ss & 1) * STG);
        const uint32_t pb = base + (uint32_t)(((ss + 1) & 1) * STG);

        asm volatile("bar.sync 1, 256;" ::: "memory");   // A-region of pb free
        if (ss < 35) load_A(ss + 1, pb);
        asm volatile("bar.sync 2, 256;" ::: "memory");   // B-region of pb free
        if (ss < 35) load_B(ss + 1, pb);                 // includes commit
        else asm volatile("cp.async.commit_group;" ::: "memory");

        // ---- ksteps 0..2 ----
#pragma unroll
        for (int k = 0; k < 3; k++) {
            const uint32_t xr = (uint32_t)(k << 5);
            uint32_t a[4][4];
#pragma unroll
            for (int mi = 0; mi < 4; mi++) ldsm_x4(a[mi], sb + (rA[mi] ^ xr));
#pragma unroll
            for (int pi = 0; pi < 3; pi++) {
                uint32_t b[4];
                ldsm_x4(b, sb + (rB[pi] ^ xr));
#pragma unroll
                for (int mi = 0; mi < 4; mi++) {
                    mma16816(acc[mi][2 * pi],     a[mi][0], a[mi][1], a[mi][2], a[mi][3], b[0], b[1]);
                    mma16816(acc[mi][2 * pi + 1], a[mi][0], a[mi][1], a[mi][2], a[mi][3], b[2], b[3]);
                }
            }
            uint32_t b6[2];
            ldsm_x2(b6, sb + (rB[3] ^ xr));
#pragma unroll
            for (int mi = 0; mi < 4; mi++)
                mma16816(acc[mi][6], a[mi][0], a[mi][1], a[mi][2], a[mi][3], b6[0], b6[1]);
        }

        // ---- kstep 3: arrive-after-last-read placement ----
        {
            const uint32_t xr = 0x60u;
            uint32_t a[4][4];
#pragma unroll
            for (int mi = 0; mi < 4; mi++) ldsm_x4(a[mi], sb + (rA[mi] ^ xr));
            asm volatile("bar.arrive 1, 256;" ::: "memory");   // A-region reads done

            uint32_t b6[2];
            ldsm_x2(b6, sb + (rB[3] ^ xr));
#pragma unroll
            for (int mi = 0; mi < 4; mi++)
                mma16816(acc[mi][6], a[mi][0], a[mi][1], a[mi][2], a[mi][3], b6[0], b6[1]);
#pragma unroll
            for (int pi = 0; pi < 2; pi++) {
                uint32_t b[4];
                ldsm_x4(b, sb + (rB[pi] ^ xr));
#pragma unroll
                for (int mi = 0; mi < 4; mi++) {
                    mma16816(acc[mi][2 * pi],     a[mi][0], a[mi][1], a[mi][2], a[mi][3], b[0], b[1]);
                    mma16816(acc[mi][2 * pi + 1], a[mi][0], a[mi][1], a[mi][2], a[mi][3], b[2], b[3]);
                }
            }
            uint32_t b2[4];
            ldsm_x4(b2, sb + (rB[2] ^ xr));                    // last B-region read
            asm volatile("cp.async.wait_group 0;" ::: "memory"); // own G_{ss+1} landed
            asm volatile("bar.arrive 2, 256;" ::: "memory");   // B-region reads done
#pragma unroll
            for (int mi = 0; mi < 4; mi++) {
                mma16816(acc[mi][4], a[mi][0], a[mi][1], a[mi][2], a[mi][3], b2[0], b2[1]);
                mma16816(acc[mi][5], a[mi][0], a[mi][1], a[mi][2], a[mi][3], b2[2], b2[3]);
            }
        }
    }

    // ---- epilogue: registers -> gmem (float2), + binarized bias ----
    const int h = h0 + wn;
#pragma unroll
    for (int mi = 0; mi < 4; mi++) {
        int mlo = mb * 128 + wm * 64 + mi * 16 + g;
        float blo = (bias[mlo]     >= 0.f) ? 1.f : -1.f;
        float bhi = (bias[mlo + 8] >= 0.f) ? 1.f : -1.f;
        size_t olo = ((size_t)(n * 256 + mlo)) * 3136 + h * 56;
        size_t ohi = olo + (size_t)8 * 3136;
#pragma unroll
        for (int ni = 0; ni < 7; ni++) {
            int w = ni * 8 + 2 * t;
            float2 v0 = make_float2(acc[mi][ni][0] + blo, acc[mi][ni][1] + blo);
            float2 v1 = make_float2(acc[mi][ni][2] + bhi, acc[mi][ni][3] + bhi);
            *reinterpret_cast<float2*>(out + olo + w) = v0;
            *reinterpret_cast<float2*>(out + ohi + w) = v1;
        }
    }
}

// ====================== launch ======================
extern "C" void kernel_launch(void* const* d_in, const int* in_sizes, int n_in,
                              void* d_out, int out_size) {
    const float* x    = (const float*)d_in[0];
    const float* w    = (const float*)d_in[1];
    const float* bias = (const float*)d_in[2];
    float* out        = (float*)d_out;

    cudaFuncSetAttribute(bconv_main_kernel,
                         cudaFuncAttributeMaxDynamicSharedMemorySize, SMEM_DYN);

    zero_border_kernel<<<32, 256>>>();
    prep_x_kernel<<<32 * 56 * 2, 256>>>(x);
    prep_w_kernel<<<2304, 256>>>(w);
    bconv_main_kernel<<<1792, 128, SMEM_DYN>>>(bias, out);
}

// round 16
// speedup vs baseline: 1.0518x; 1.0219x over previous
#include <cuda_runtime.h>
#include <cuda_fp16.h>
#include <cstdint>

// ====================== tile/pipeline constants ======================
// CTA: 128 threads (4 warps 2x2), tile 128 couts x 112 pixels (2 output rows)
// Superstage = 64 ci: A 16384 B (128 rows x 128B) + B 14336 B (112 rows x 128B)
#define STG      30720
#define STAGES   2
#define SMEM_DYN (STAGES * STG + 128)

// ====================== device scratch ======================
__device__ __align__(16) __half g_x[(size_t)32 * 58 * 58 * 256];  // padded NHWC fp16
__device__ __align__(16) __half g_w[(size_t)9 * 256 * 256];       // [tap][co][ci] = +-1

// ====================== helpers ======================
__device__ __forceinline__ uint32_t smem_u32(const void* p) {
    uint32_t a;
    asm("{ .reg .u64 t; cvta.to.shared.u64 t, %1; cvt.u32.u64 %0, t; }" : "=r"(a) : "l"(p));
    return a;
}
__device__ __forceinline__ void cp16(uint32_t d, const void* s) {
    asm volatile("cp.async.cg.shared.global [%0], [%1], 16;" :: "r"(d), "l"(s) : "memory");
}
__device__ __forceinline__ void ldsm_x4(uint32_t* r, uint32_t a) {
    asm volatile("ldmatrix.sync.aligned.m8n8.x4.shared.b16 {%0,%1,%2,%3}, [%4];"
                 : "=r"(r[0]), "=r"(r[1]), "=r"(r[2]), "=r"(r[3]) : "r"(a));
}
__device__ __forceinline__ void ldsm_x2(uint32_t* r, uint32_t a) {
    asm volatile("ldmatrix.sync.aligned.m8n8.x2.shared.b16 {%0,%1}, [%2];"
                 : "=r"(r[0]), "=r"(r[1]) : "r"(a));
}
__device__ __forceinline__ void mma16816(float* c, uint32_t a0, uint32_t a1, uint32_t a2,
                                         uint32_t a3, uint32_t b0, uint32_t b1) {
    asm volatile(
        "mma.sync.aligned.m16n8k16.row.col.f32.f16.f16.f32 "
        "{%0,%1,%2,%3}, {%4,%5,%6,%7}, {%8,%9}, {%0,%1,%2,%3};"
        : "+f"(c[0]), "+f"(c[1]), "+f"(c[2]), "+f"(c[3])
        : "r"(a0), "r"(a1), "r"(a2), "r"(a3), "r"(b0), "r"(b1));
}

// ====================== fused prep kernel ======================
// blocks [0,3584): x transpose NCHW f32 -> padded NHWC fp16
// blocks [3584,3616): pad-border zeroing (one block per image)
// blocks [3616,4192): weight binarize, 4 elems/thread via float4
__global__ void prep_all_kernel(const float* __restrict__ x, const float* __restrict__ w) {
    const int b = blockIdx.x;
    if (b < 3584) {
        __shared__ float tile[128][57];
        const int ch = b & 1;
        const int h  = (b >> 1) % 56;
        const int n  = (b >> 1) / 56;
        const float* src = x + (size_t)(n * 256 + ch * 128) * 3136 + h * 56;
        for (int i = threadIdx.x; i < 128 * 56; i += 256) {
            int ci = i / 56, ww = i - 56 * ci;
            tile[ci][ww] = src[(size_t)ci * 3136 + ww];
        }
        __syncthreads();
        __half* dst = g_x + (size_t)n * 861184 + ((h + 1) * 58 + 1) * 256;
        for (int j = threadIdx.x; j < 64 * 56; j += 256) {
            int ww = j >> 6, cp = j & 63;
            int ci = ch * 128 + 2 * cp;
            __half2 v = __floats2half2_rn(tile[2 * cp][ww], tile[2 * cp + 1][ww]);
            *reinterpret_cast<__half2*>(dst + (size_t)ww * 256 + ci) = v;
        }
    } else if (b < 3616) {
        const int n = b - 3584;
        __half* xb = g_x + (size_t)n * 861184;
        for (int c = threadIdx.x; c < 7296; c += 256) { // 228 border px * 32 uint4
            int px = c >> 5, q = c & 31;
            int h, ww;
            if (px < 58)       { h = 0;        ww = px; }
            else if (px < 116) { h = 57;       ww = px - 58; }
            else if (px < 172) { h = px - 115; ww = 0; }
            else               { h = px - 171; ww = 57; }
            reinterpret_cast<uint4*>(xb + ((size_t)h * 58 + ww) * 256)[q] =
                make_uint4(0u, 0u, 0u, 0u);
        }
    } else {
        // weight: idx = co*2304 + ci*9 + tap -> g_w[tap][co][ci]
        int i0 = (b - 3616) * 1024 + threadIdx.x * 4;
        float4 v = *reinterpret_cast<const float4*>(w + i0);
        float vv[4] = {v.x, v.y, v.z, v.w};
#pragma unroll
        for (int e = 0; e < 4; e++) {
            int idx = i0 + e;
            int co  = idx / 2304;
            int r   = idx - co * 2304;
            int ci  = r / 9;
            int tap = r - ci * 9;
            g_w[(size_t)(tap * 256 + co) * 256 + ci] = __float2half(vv[e] >= 0.f ? 1.f : -1.f);
        }
    }
}

// ====================== main kernel (exact R11 structure) ======================
// grid 1792 = 2 cout-halves * 28 row-pairs * 32 images; 128 threads (4 warps 2x2).
// Warp tile 64x56: 4 m16-frags x 7 n8-frags, 4 ksteps per 64-ci superstage.
// Smem: 128B rows, 16B bank index = chunk ^ (row&7) (ldmatrix conflict-free);
// kstep k selects chunks {2k,2k+1} via address XOR (k<<5).
__global__ void __launch_bounds__(128, 3)
bconv_main_kernel(const float* __restrict__ bias, float* __restrict__ out) {
    extern __shared__ char dsm[];
    const uint32_t base = (smem_u32(dsm) + 127u) & ~127u;

    const int tid  = threadIdx.x;
    const int lane = tid & 31;
    const int wid  = tid >> 5;
    const int g    = lane >> 2;
    const int t    = lane & 3;
    const int wm   = wid >> 1;     // 0..1  (m warp half)
    const int wn   = wid & 1;      // 0..1  (output row within pair)

    const int bid = blockIdx.x;
    const int mb  = bid & 1;
    const int rp  = (bid >> 1) % 28;
    const int n   = bid / 56;
    const int h0  = rp * 2;

    const __half* xn = g_x + (size_t)n * 861184;

    // ---- cp.async affine bases (16B chunks; row&7 invariant across i since step=16) ----
    const int r0  = tid >> 3;                 // base row 0..15
    const int cbk = tid & 7;                  // chunk within 128B row
    const uint32_t cb8 = (uint32_t)(cbk * 8); // element offset of chunk
    const uint32_t swz = (uint32_t)((cbk ^ (r0 & 7)) << 4);
    const uint32_t aD0 = (uint32_t)(r0 * 128) + swz;
    const uint32_t bD0 = 16384u + aD0;
    const uint32_t aG0 = (uint32_t)((mb * 128 + r0) * 256) + cb8;

    auto load_ss = [&](int ss, uint32_t sb) {
        int tap = ss >> 2, kc2 = ss & 3;      // 64-ci chunk within tap
        int dh  = tap / 3, dw = tap - 3 * dh;
        const __half* wp = g_w + tap * 65536 + kc2 * 64 + aG0;
#pragma unroll
        for (int i = 0; i < 8; i++)           // A: 128 rows, this thread rows r0+16i
            cp16(sb + aD0 + (uint32_t)(i * 2048), wp + i * 4096);
        uint32_t bgc = (uint32_t)((((h0 + dh) * 58 + dw) * 256) + kc2 * 64) + cb8;
#pragma unroll
        for (int i = 0; i < 7; i++) {         // B: 112 pixel rows, rows r0+16i
            int prow = r0 + 16 * i;
            uint32_t off = bgc + (uint32_t)(prow * 256) + (prow >= 56 ? 512u : 0u);
            cp16(sb + bD0 + (uint32_t)(i * 2048), xn + off);
        }
        asm volatile("cp.async.commit_group;" ::: "memory");
    };

    // ---- ldmatrix lane addresses (kstep 0; kstep k = XOR k<<5) ----
    uint32_t rA[4];
    {
        int rl   = (lane & 7) + ((lane >> 3) & 1) * 8;
        int half = lane >> 4;
#pragma unroll
        for (int mi = 0; mi < 4; mi++) {
            int row = wm * 64 + mi * 16 + rl;
            rA[mi] = (uint32_t)(row * 128 + ((half ^ (row & 7)) << 4));
        }
    }
    uint32_t rB[4];
    {
        int pl   = (lane & 7) + (lane >> 4) * 8;
        int half = (lane >> 3) & 1;
#pragma unroll
        for (int pi = 0; pi < 3; pi++) {
            int pix = wn * 56 + pi * 16 + pl;
            rB[pi] = 16384u + (uint32_t)(pix * 128 + ((half ^ (pix & 7)) << 4));
        }
        int pix6 = wn * 56 + 48 + (lane & 7);
        rB[3] = 16384u + (uint32_t)(pix6 * 128 + ((half ^ (pix6 & 7)) << 4));
    }

    float acc[4][7][4];
#pragma unroll
    for (int mi = 0; mi < 4; mi++)
#pragma unroll
        for (int ni = 0; ni < 7; ni++)
#pragma unroll
            for (int k = 0; k < 4; k++) acc[mi][ni][k] = 0.f;

    // ---- prologue: superstage 0 ----
    load_ss(0, base);
    asm volatile("cp.async.wait_group 0;" ::: "memory");
    __syncthreads();

    // ---- mainloop: 36 superstages, 2 buffers ----
    for (int ss = 0; ss < 36; ss++) {
        if (ss < 35) load_ss(ss + 1, base + (uint32_t)(((ss + 1) & 1) * STG));

        const uint32_t sb = base + (uint32_t)((ss & 1) * STG);
#pragma unroll
        for (int k = 0; k < 4; k++) {
            const uint32_t xr = (uint32_t)(k << 5);
            uint32_t a[4][4];
#pragma unroll
            for (int mi = 0; mi < 4; mi++) ldsm_x4(a[mi], sb + (rA[mi] ^ xr));
#pragma unroll
            for (int pi = 0; pi < 3; pi++) {
                uint32_t bfr[4];
                ldsm_x4(bfr, sb + (rB[pi] ^ xr));
#pragma unroll
                for (int mi = 0; mi < 4; mi++) {
                    mma16816(acc[mi][2 * pi],     a[mi][0], a[mi][1], a[mi][2], a[mi][3], bfr[0], bfr[1]);
                    mma16816(acc[mi][2 * pi + 1], a[mi][0], a[mi][1], a[mi][2], a[mi][3], bfr[2], bfr[3]);
                }
            }
            uint32_t b6[2];
            ldsm_x2(b6, sb + (rB[3] ^ xr));
#pragma unroll
            for (int mi = 0; mi < 4; mi++)
                mma16816(acc[mi][6], a[mi][0], a[mi][1], a[mi][2], a[mi][3], b6[0], b6[1]);
        }
        asm volatile("cp.async.wait_group 0;" ::: "memory");
        __syncthreads();
    }

    // ---- epilogue: registers -> gmem (float2), + binarized bias ----
    const int h = h0 + wn;
#pragma unroll
    for (int mi = 0; mi < 4; mi++) {
        int mlo = mb * 128 + wm * 64 + mi * 16 + g;
        float blo = (bias[mlo]     >= 0.f) ? 1.f : -1.f;
        float bhi = (bias[mlo + 8] >= 0.f) ? 1.f : -1.f;
        size_t olo = ((size_t)(n * 256 + mlo)) * 3136 + h * 56;
        size_t ohi = olo + (size_t)8 * 3136;
#pragma unroll
        for (int ni = 0; ni < 7; ni++) {
            int ww = ni * 8 + 2 * t;
            float2 v0 = make_float2(acc[mi][ni][0] + blo, acc[mi][ni][1] + blo);
            float2 v1 = make_float2(acc[mi][ni][2] + bhi, acc[mi][ni][3] + bhi);
            *reinterpret_cast<float2*>(out + olo + ww) = v0;
            *reinterpret_cast<float2*>(out + ohi + ww) = v1;
        }
    }
}

// ====================== launch ======================
extern "C" void kernel_launch(void* const* d_in, const int* in_sizes, int n_in,
                              void* d_out, int out_size) {
    const float* x    = (const float*)d_in[0];
    const float* w    = (const float*)d_in[1];
    const float* bias = (const float*)d_in[2];
    float* out        = (float*)d_out;

    cudaFuncSetAttribute(bconv_main_kernel,
                         cudaFuncAttributeMaxDynamicSharedMemorySize, SMEM_DYN);

    prep_all_kernel<<<4192, 256>>>(x, w);
    bconv_main_kernel<<<1792, 128, SMEM_DYN>>>(bias, out);
}